// round 1
// baseline (speedup 1.0000x reference)
#include <cuda_runtime.h>
#include <math.h>

#define BB 32
#define NN 128
#define OBSD 32
#define HD 128
#define MD 128
#define NLAYERS 3
#define ROWS (BB*NN)      // 4096
#define TR 16             // rows per block for the small row-tile kernels

// ---------------- scratch (static device globals; no allocation) -----------
__device__ float g_z[ROWS*HD];       // node state
__device__ float g_A[ROWS*MD];       // z @ w1a + b1   (row-major)
__device__ float g_BpT[BB*MD*NN];    // (z @ w1b) transposed per batch: [b][f][j]
__device__ float g_S[ROWS*MD];       // sum_{j!=i} H2[j,:]

// ---------------- encoder: obs(4096x32) -> H -> H -> H --------------------
__global__ void enc_kernel(const float* __restrict__ obs,
                           const float* __restrict__ w1, const float* __restrict__ b1,
                           const float* __restrict__ w2, const float* __restrict__ b2,
                           const float* __restrict__ w3, const float* __restrict__ b3)
{
    __shared__ float s_in[TR][OBSD];
    __shared__ float s_h[TR][HD];
    __shared__ float s_h2[TR][HD];
    const int c = threadIdx.x;           // 0..127 (output column)
    const int row0 = blockIdx.x * TR;

    for (int idx = c; idx < TR*OBSD; idx += HD)
        s_in[idx / OBSD][idx % OBSD] = obs[row0*OBSD + idx];
    __syncthreads();

    float acc[TR];
#pragma unroll
    for (int r = 0; r < TR; r++) acc[r] = b1[c];
    for (int k = 0; k < OBSD; k++) {
        float wv = w1[k*HD + c];
#pragma unroll
        for (int r = 0; r < TR; r++) acc[r] += s_in[r][k]*wv;
    }
#pragma unroll
    for (int r = 0; r < TR; r++) s_h[r][c] = fmaxf(acc[r], 0.f);
    __syncthreads();

#pragma unroll
    for (int r = 0; r < TR; r++) acc[r] = b2[c];
    for (int k = 0; k < HD; k++) {
        float wv = w2[k*HD + c];
#pragma unroll
        for (int r = 0; r < TR; r++) acc[r] += s_h[r][k]*wv;
    }
#pragma unroll
    for (int r = 0; r < TR; r++) s_h2[r][c] = fmaxf(acc[r], 0.f);
    __syncthreads();

#pragma unroll
    for (int r = 0; r < TR; r++) acc[r] = b3[c];
    for (int k = 0; k < HD; k++) {
        float wv = w3[k*HD + c];
#pragma unroll
        for (int r = 0; r < TR; r++) acc[r] += s_h2[r][k]*wv;
    }
#pragma unroll
    for (int r = 0; r < TR; r++) g_z[(row0+r)*HD + c] = acc[r];
}

// -------- per-node projections for message layer 1 --------
// A   = z @ w1[0:H]   + b1   (row-major)
// BpT = z @ w1[H:2H]          (stored transposed per batch: [b][f][j])
__global__ void pairproj_kernel(const float* __restrict__ w1,
                                const float* __restrict__ b1)
{
    __shared__ float s_z[TR][HD];
    const int c = threadIdx.x;
    const int row0 = blockIdx.x * TR;
    for (int r = 0; r < TR; r++)
        s_z[r][c] = g_z[(row0+r)*HD + c];
    __syncthreads();

    float accA[TR], accB[TR];
#pragma unroll
    for (int r = 0; r < TR; r++) { accA[r] = b1[c]; accB[r] = 0.f; }
    for (int k = 0; k < HD; k++) {
        float wa = w1[k*MD + c];
        float wb = w1[(HD + k)*MD + c];
#pragma unroll
        for (int r = 0; r < TR; r++) {
            float zv = s_z[r][k];
            accA[r] += zv*wa;
            accB[r] += zv*wb;
        }
    }
    const int b  = row0 / NN;
    const int j0 = row0 % NN;
#pragma unroll
    for (int r = 0; r < TR; r++) {
        g_A[(row0+r)*MD + c] = accA[r];
        g_BpT[b*(MD*NN) + c*NN + (j0+r)] = accB[r];
    }
}

// -------- hot kernel: one block per (b,i) --------
// Build H1[j,f] = relu(A[i,f] + Bp[j,f] + d_ij * w1d[f])   (f-major in smem)
// GEMM+reduce:   S[i,m] = sum_{j != i} relu( (H1 @ w2)[j,m] + b2[m] )
__global__ void __launch_bounds__(512, 1) pair_kernel(
    const float* __restrict__ pos,
    const float* __restrict__ w1d,
    const float* __restrict__ w2,
    const float* __restrict__ b2)
{
    extern __shared__ float smem[];
    float* H1s  = smem;            // 16384 floats : [f][j]
    float* W2s  = smem + 16384;    // 16384 floats : [k][m]
    float* dsh  = smem + 32768;    // 128
    float* sred = smem + 32896;    // 16*128

    const int tid   = threadIdx.x;
    const int bi    = blockIdx.x;      // b*128 + i
    const int b     = bi >> 7;
    const int inode = bi & 127;

    // stage w2 into smem (reused 128x per block)
    {
        const float4* src = (const float4*)w2;
        float4* dst = (float4*)W2s;
        for (int idx = tid; idx < 4096; idx += 512) dst[idx] = src[idx];
    }
    // pairwise distances to node i
    if (tid < NN) {
        const float2 pi = ((const float2*)pos)[b*NN + inode];
        const float2 pj = ((const float2*)pos)[b*NN + tid];
        float dx = pi.x - pj.x, dy = pi.y - pj.y;
        dsh[tid] = sqrtf(dx*dx + dy*dy);
    }
    __syncthreads();

    // build H1 (f-major, coalesced reads of BpT, broadcast A/w1d)
    {
        const float* Arow = g_A + bi*MD;
        const float* Bp   = g_BpT + b*(MD*NN);
#pragma unroll
        for (int it = 0; it < 32; it++) {
            int idx = it*512 + tid;       // idx = f*128 + j
            int f = idx >> 7;
            int j = idx & 127;
            float v = Arow[f] + Bp[idx] + dsh[j]*w1d[f];
            H1s[idx] = fmaxf(v, 0.f);
        }
    }
    __syncthreads();

    // 128x128x128 GEMM, thread tile 8(j) x 4(m), H1 reads are warp-broadcast
    const int tidm = tid & 31;
    const int tidj = tid >> 5;
    const int m0 = tidm*4;
    const int j0 = tidj*8;
    float acc[8][4];
#pragma unroll
    for (int jj = 0; jj < 8; jj++)
#pragma unroll
        for (int mm = 0; mm < 4; mm++) acc[jj][mm] = 0.f;

#pragma unroll 8
    for (int k = 0; k < 128; k++) {
        float4 wv = *(const float4*)&W2s[k*128 + m0];
        float4 ha = *(const float4*)&H1s[k*128 + j0];
        float4 hb = *(const float4*)&H1s[k*128 + j0 + 4];
        float hj[8] = {ha.x, ha.y, ha.z, ha.w, hb.x, hb.y, hb.z, hb.w};
#pragma unroll
        for (int jj = 0; jj < 8; jj++) {
            acc[jj][0] += hj[jj]*wv.x;
            acc[jj][1] += hj[jj]*wv.y;
            acc[jj][2] += hj[jj]*wv.z;
            acc[jj][3] += hj[jj]*wv.w;
        }
    }

    // epilogue: +b2, relu, reduce over j (skip j == i)
    float4 b2v = *(const float4*)&b2[m0];
    float bias[4] = {b2v.x, b2v.y, b2v.z, b2v.w};
#pragma unroll
    for (int mm = 0; mm < 4; mm++) {
        float s = 0.f;
#pragma unroll
        for (int jj = 0; jj < 8; jj++) {
            float v = fmaxf(acc[jj][mm] + bias[mm], 0.f);
            s += (j0 + jj != inode) ? v : 0.f;
        }
        sred[tidj*128 + m0 + mm] = s;
    }
    __syncthreads();
    if (tid < 128) {
        float s = 0.f;
#pragma unroll
        for (int t = 0; t < 16; t++) s += sred[t*128 + tid];
        g_S[bi*MD + tid] = s;
    }
}

// -------- msg = S @ w3 + 127*b3 ; then update MLP (fused) --------
__global__ void upd_kernel(const float* __restrict__ w3, const float* __restrict__ b3,
                           const float* __restrict__ uw1, const float* __restrict__ ub1,
                           const float* __restrict__ uw2, const float* __restrict__ ub2,
                           const float* __restrict__ uw3, const float* __restrict__ ub3,
                           float* __restrict__ out, int write_out)
{
    __shared__ float sS[TR][MD];
    __shared__ float sZ[TR][HD];
    __shared__ float sMsg[TR][MD];
    __shared__ float sT[TR][HD];
    const int c = threadIdx.x;
    const int row0 = blockIdx.x * TR;

    for (int r = 0; r < TR; r++) {
        sS[r][c] = g_S[(row0+r)*MD + c];
        sZ[r][c] = g_z[(row0+r)*HD + c];
    }
    __syncthreads();

    float acc[TR];
    // msg = S @ w3 + 127*b3
#pragma unroll
    for (int r = 0; r < TR; r++) acc[r] = 127.0f * b3[c];
    for (int k = 0; k < MD; k++) {
        float wv = w3[k*MD + c];
#pragma unroll
        for (int r = 0; r < TR; r++) acc[r] += sS[r][k]*wv;
    }
#pragma unroll
    for (int r = 0; r < TR; r++) sMsg[r][c] = acc[r];
    __syncthreads();

    // u1 = relu(z@uw1[0:H] + msg@uw1[H:H+M] + ub1)
#pragma unroll
    for (int r = 0; r < TR; r++) acc[r] = ub1[c];
    for (int k = 0; k < HD; k++) {
        float wv = uw1[k*HD + c];
#pragma unroll
        for (int r = 0; r < TR; r++) acc[r] += sZ[r][k]*wv;
    }
    for (int k = 0; k < MD; k++) {
        float wv = uw1[(HD + k)*HD + c];
#pragma unroll
        for (int r = 0; r < TR; r++) acc[r] += sMsg[r][k]*wv;
    }
#pragma unroll
    for (int r = 0; r < TR; r++) sT[r][c] = fmaxf(acc[r], 0.f);
    __syncthreads();

    // u2 = relu(u1 @ uw2 + ub2)  (write into sMsg, free after previous sync)
#pragma unroll
    for (int r = 0; r < TR; r++) acc[r] = ub2[c];
    for (int k = 0; k < HD; k++) {
        float wv = uw2[k*HD + c];
#pragma unroll
        for (int r = 0; r < TR; r++) acc[r] += sT[r][k]*wv;
    }
#pragma unroll
    for (int r = 0; r < TR; r++) sMsg[r][c] = fmaxf(acc[r], 0.f);
    __syncthreads();

    // z_new = u2 @ uw3 + ub3
#pragma unroll
    for (int r = 0; r < TR; r++) acc[r] = ub3[c];
    for (int k = 0; k < HD; k++) {
        float wv = uw3[k*HD + c];
#pragma unroll
        for (int r = 0; r < TR; r++) acc[r] += sMsg[r][k]*wv;
    }
    if (write_out) {
#pragma unroll
        for (int r = 0; r < TR; r++) out[(row0+r)*HD + c] = acc[r];
    } else {
#pragma unroll
        for (int r = 0; r < TR; r++) g_z[(row0+r)*HD + c] = acc[r];
    }
}

extern "C" void kernel_launch(void* const* d_in, const int* in_sizes, int n_in,
                              void* d_out, int out_size)
{
    const float* obs    = (const float*)d_in[0];
    const float* pos    = (const float*)d_in[1];
    const float* enc_w1 = (const float*)d_in[2];
    const float* enc_b1 = (const float*)d_in[3];
    const float* enc_w2 = (const float*)d_in[4];
    const float* enc_b2 = (const float*)d_in[5];
    const float* enc_w3 = (const float*)d_in[6];
    const float* enc_b3 = (const float*)d_in[7];
    const float* msg_w1 = (const float*)d_in[8];
    const float* msg_b1 = (const float*)d_in[9];
    const float* msg_w2 = (const float*)d_in[10];
    const float* msg_b2 = (const float*)d_in[11];
    const float* msg_w3 = (const float*)d_in[12];
    const float* msg_b3 = (const float*)d_in[13];
    const float* upd_w1 = (const float*)d_in[14];
    const float* upd_b1 = (const float*)d_in[15];
    const float* upd_w2 = (const float*)d_in[16];
    const float* upd_b2 = (const float*)d_in[17];
    const float* upd_w3 = (const float*)d_in[18];
    const float* upd_b3 = (const float*)d_in[19];
    float* out = (float*)d_out;

    const int smem_pair = (16384 + 16384 + 128 + 16*128) * (int)sizeof(float);
    cudaFuncSetAttribute(pair_kernel, cudaFuncAttributeMaxDynamicSharedMemorySize, smem_pair);

    enc_kernel<<<ROWS/TR, HD>>>(obs, enc_w1, enc_b1, enc_w2, enc_b2, enc_w3, enc_b3);

    for (int l = 0; l < NLAYERS; l++) {
        const float* w1 = msg_w1 + (size_t)l*(2*HD+1)*MD;
        const float* b1 = msg_b1 + (size_t)l*MD;
        const float* w2 = msg_w2 + (size_t)l*MD*MD;
        const float* b2 = msg_b2 + (size_t)l*MD;
        const float* w3 = msg_w3 + (size_t)l*MD*MD;
        const float* b3 = msg_b3 + (size_t)l*MD;
        const float* uw1 = upd_w1 + (size_t)l*(HD+MD)*HD;
        const float* ub1 = upd_b1 + (size_t)l*HD;
        const float* uw2 = upd_w2 + (size_t)l*HD*HD;
        const float* ub2 = upd_b2 + (size_t)l*HD;
        const float* uw3 = upd_w3 + (size_t)l*HD*HD;
        const float* ub3 = upd_b3 + (size_t)l*HD;

        pairproj_kernel<<<ROWS/TR, HD>>>(w1, b1);
        pair_kernel<<<ROWS, 512, smem_pair>>>(pos, w1 + 2*HD*MD, w2, b2);
        upd_kernel<<<ROWS/TR, HD>>>(w3, b3, uw1, ub1, uw2, ub2, uw3, ub3,
                                    out, (l == NLAYERS-1) ? 1 : 0);
    }
}